// round 3
// baseline (speedup 1.0000x reference)
#include <cuda_runtime.h>
#include <math.h>

#define S_LEN 256
#define B_SZ  16
#define V_SZ  32000
#define E_SZ  512
#define H_SZ  1024
#define M_SZ  (S_LEN * B_SZ)   // 4096

// Scratch (no allocations allowed): x / pred storage and tanh(pred) storage.
__device__ float g_x [M_SZ * H_SZ];   // 16 MB: x[s,b,h] (input projection)
__device__ float g_th[M_SZ * H_SZ];   // 16 MB: tanh(pred[s,b,h])

// ---------------------------------------------------------------------------
// Generic NT SGEMM: C[M,N] = A[M,K] * B[N,K]^T (+ bias[N])
// A optionally gathered through `tokens` (A treated as emb[V,K], row = tokens[m]).
// BM=BN=128, BK=8, 256 threads, 8x8 per-thread register tile, double-buffered.
// Requires M%128==0, N%128==0, K%8==0 (true for all uses here).
// ---------------------------------------------------------------------------
template<bool GATHER>
__global__ void __launch_bounds__(256) sgemm128_nt(
    const float* __restrict__ A,
    const float* __restrict__ B,
    const float* __restrict__ bias,
    const int*   __restrict__ tokens,
    float* __restrict__ C,
    int N, int K)
{
    __shared__ float As[2][8][128];
    __shared__ float Bs[2][8][128];

    const int tid = threadIdx.x;
    const int bm  = blockIdx.y;
    const int bn  = blockIdx.x;

    // global-load mapping: each thread loads one float4 of A and one of B per tile
    const int lrow = tid >> 1;            // 0..127
    const int lk   = (tid & 1) << 2;      // 0 or 4

    const float* Arow;
    if (GATHER) {
        const int tok = tokens[bm * 128 + lrow];
        Arow = A + (size_t)tok * K;
    } else {
        Arow = A + (size_t)(bm * 128 + lrow) * K;
    }
    const float* Brow = B + (size_t)(bn * 128 + lrow) * K;

    const int tx = tid & 15;              // N-direction
    const int ty = tid >> 4;              // M-direction

    float acc[8][8];
#pragma unroll
    for (int i = 0; i < 8; i++)
#pragma unroll
        for (int j = 0; j < 8; j++) acc[i][j] = 0.f;

    // prologue: load tile 0 into buffer 0
    {
        float4 a4 = *(const float4*)(Arow + lk);
        float4 b4 = *(const float4*)(Brow + lk);
        As[0][lk + 0][lrow] = a4.x; As[0][lk + 1][lrow] = a4.y;
        As[0][lk + 2][lrow] = a4.z; As[0][lk + 3][lrow] = a4.w;
        Bs[0][lk + 0][lrow] = b4.x; Bs[0][lk + 1][lrow] = b4.y;
        Bs[0][lk + 2][lrow] = b4.z; Bs[0][lk + 3][lrow] = b4.w;
    }
    __syncthreads();

    const int nt = K >> 3;
    for (int t = 0; t < nt; ++t) {
        const int cur = t & 1;
        float4 na, nb;
        if (t + 1 < nt) {
            na = *(const float4*)(Arow + (t + 1) * 8 + lk);
            nb = *(const float4*)(Brow + (t + 1) * 8 + lk);
        }
#pragma unroll
        for (int k = 0; k < 8; k++) {
            float af[8], bf[8];
            *(float4*)(af)     = *(const float4*)&As[cur][k][ty * 8];
            *(float4*)(af + 4) = *(const float4*)&As[cur][k][ty * 8 + 4];
            *(float4*)(bf)     = *(const float4*)&Bs[cur][k][tx * 8];
            *(float4*)(bf + 4) = *(const float4*)&Bs[cur][k][tx * 8 + 4];
#pragma unroll
            for (int i = 0; i < 8; i++)
#pragma unroll
                for (int j = 0; j < 8; j++)
                    acc[i][j] += af[i] * bf[j];
        }
        if (t + 1 < nt) {
            const int nxt = cur ^ 1;
            As[nxt][lk + 0][lrow] = na.x; As[nxt][lk + 1][lrow] = na.y;
            As[nxt][lk + 2][lrow] = na.z; As[nxt][lk + 3][lrow] = na.w;
            Bs[nxt][lk + 0][lrow] = nb.x; Bs[nxt][lk + 1][lrow] = nb.y;
            Bs[nxt][lk + 2][lrow] = nb.z; Bs[nxt][lk + 3][lrow] = nb.w;
            __syncthreads();
        }
    }

    // epilogue
    const int gm0 = bm * 128 + ty * 8;
    const int gn0 = bn * 128 + tx * 8;
    float bb[8];
    if (bias) {
        *(float4*)(bb)     = *(const float4*)(bias + gn0);
        *(float4*)(bb + 4) = *(const float4*)(bias + gn0 + 4);
    } else {
#pragma unroll
        for (int j = 0; j < 8; j++) bb[j] = 0.f;
    }
#pragma unroll
    for (int i = 0; i < 8; i++) {
        float4 v0, v1;
        v0.x = acc[i][0] + bb[0]; v0.y = acc[i][1] + bb[1];
        v0.z = acc[i][2] + bb[2]; v0.w = acc[i][3] + bb[3];
        v1.x = acc[i][4] + bb[4]; v1.y = acc[i][5] + bb[5];
        v1.z = acc[i][6] + bb[6]; v1.w = acc[i][7] + bb[7];
        float* crow = C + (size_t)(gm0 + i) * N + gn0;
        *(float4*)(crow)     = v0;
        *(float4*)(crow + 4) = v1;
    }
}

// ---------------------------------------------------------------------------
// tanh of x[0] -> th[0]
// ---------------------------------------------------------------------------
__global__ void tanh0_kernel()
{
    int i = blockIdx.x * blockDim.x + threadIdx.x;
    if (i < B_SZ * H_SZ) g_th[i] = tanhf(g_x[i]);
}

// ---------------------------------------------------------------------------
// One recurrence step:
//   th[s][b][n] = tanh( x[s][b][n] + sum_k th[s-1][b][k] * W_hh[n][k] )
// grid = 64 CTAs (16 output columns each), 256 threads = 16b x 16n, 1 out/thread.
// ---------------------------------------------------------------------------
__global__ void __launch_bounds__(256) step_kernel(const float* __restrict__ W_hh, int s)
{
    __shared__ float sA[16][68];   // th_prev tile [b][k], padded (68*4 bytes, 16B aligned rows)
    __shared__ float sW[16][68];   // W_hh tile [n_local][k]

    const float* th_prev = g_th + (size_t)(s - 1) * B_SZ * H_SZ;
    const float* x_s     = g_x  + (size_t)s * B_SZ * H_SZ;
    float*       th_out  = g_th + (size_t)s * B_SZ * H_SZ;

    const int tid = threadIdx.x;
    const int n0  = blockIdx.x * 16;

    const int lr = tid >> 4;          // 0..15 : row for cooperative loads
    const int lc = (tid & 15) << 2;   // 0..60 : float4 column

    const int n = tid & 15;           // output column (local)
    const int b = tid >> 4;           // output batch

    float acc = 0.f;

    for (int kt = 0; kt < H_SZ; kt += 64) {
        float4 a4 = *(const float4*)(th_prev + lr * H_SZ + kt + lc);
        float4 w4 = *(const float4*)(W_hh + (size_t)(n0 + lr) * H_SZ + kt + lc);
        __syncthreads();   // previous iteration's reads must finish
        *(float4*)&sA[lr][lc] = a4;
        *(float4*)&sW[lr][lc] = w4;
        __syncthreads();
#pragma unroll
        for (int k = 0; k < 64; k += 4) {
            float4 av = *(const float4*)&sA[b][k];
            float4 wv = *(const float4*)&sW[n][k];
            acc += av.x * wv.x;
            acc += av.y * wv.y;
            acc += av.z * wv.z;
            acc += av.w * wv.w;
        }
    }

    const int h = n0 + n;
    th_out[b * H_SZ + h] = tanhf(acc + x_s[b * H_SZ + h]);
}

// ---------------------------------------------------------------------------
// kernel_launch
// inputs order: inputs(int32 [S,B]), emb [V,E], W_in [H,E], W_hh [H,H],
//               W_out [V,H], b_out [V]; output: logits fp32 [S*B, V]
// ---------------------------------------------------------------------------
extern "C" void kernel_launch(void* const* d_in, const int* in_sizes, int n_in,
                              void* d_out, int out_size)
{
    (void)in_sizes; (void)n_in; (void)out_size;
    const int*   tokens = (const int*)  d_in[0];
    const float* emb    = (const float*)d_in[1];
    const float* W_in   = (const float*)d_in[2];
    const float* W_hh   = (const float*)d_in[3];
    const float* W_out  = (const float*)d_in[4];
    const float* b_out  = (const float*)d_in[5];
    float* out = (float*)d_out;

    float *gx = nullptr, *gth = nullptr;
    cudaGetSymbolAddress((void**)&gx,  g_x);
    cudaGetSymbolAddress((void**)&gth, g_th);

    // 1) x[s,b,h] = sum_e emb[tok[s,b], e] * W_in[h, e]
    //    M=4096, N=1024, K=512
    sgemm128_nt<true><<<dim3(H_SZ / 128, M_SZ / 128), 256>>>(
        emb, W_in, nullptr, tokens, gx, H_SZ, E_SZ);

    // 2) th[0] = tanh(x[0])
    tanh0_kernel<<<(B_SZ * H_SZ + 255) / 256, 256>>>();

    // 3) recurrence: s = 1..S-1
    for (int s = 1; s < S_LEN; ++s) {
        step_kernel<<<H_SZ / 16, 256>>>(W_hh, s);
    }

    // 4) logits[m, v] = sum_k th[m, k] * W_out[v, k] + b_out[v]
    //    M=4096, N=32000, K=1024
    sgemm128_nt<false><<<dim3(V_SZ / 128, M_SZ / 128), 256>>>(
        gth, W_out, b_out, nullptr, out, V_SZ, H_SZ);
}

// round 4
// speedup vs baseline: 1.0524x; 1.0524x over previous
#include <cuda_runtime.h>
#include <math.h>

#define S_LEN 256
#define B_SZ  16
#define V_SZ  32000
#define E_SZ  512
#define H_SZ  1024
#define M_SZ  (S_LEN * B_SZ)   // 4096

// Scratch (no allocations allowed): x / pred storage and tanh(pred) storage.
__device__ float g_x [M_SZ * H_SZ];   // 16 MB: x[s,b,h] (input projection)
__device__ float g_th[M_SZ * H_SZ];   // 16 MB: tanh(pred[s,b,h])

// ---------------------------------------------------------------------------
// Generic NT SGEMM: C[M,N] = A[M,K] * B[N,K]^T (+ bias[N])
// A optionally gathered through `tokens` (A treated as emb[V,K], row = tokens[m]).
// BM=BN=128, BK=8, 256 threads, 8x8 per-thread register tile, double-buffered.
// Requires M%128==0, N%128==0, K%8==0 (true for all uses here).
// ---------------------------------------------------------------------------
template<bool GATHER>
__global__ void __launch_bounds__(256) sgemm128_nt(
    const float* __restrict__ A,
    const float* __restrict__ B,
    const float* __restrict__ bias,
    const int*   __restrict__ tokens,
    float* __restrict__ C,
    int N, int K)
{
    __shared__ float As[2][8][128];
    __shared__ float Bs[2][8][128];

    const int tid = threadIdx.x;
    const int bm  = blockIdx.y;
    const int bn  = blockIdx.x;

    // global-load mapping: each thread loads one float4 of A and one of B per tile
    const int lrow = tid >> 1;            // 0..127
    const int lk   = (tid & 1) << 2;      // 0 or 4

    const float* Arow;
    if (GATHER) {
        const int tok = tokens[bm * 128 + lrow];
        Arow = A + (size_t)tok * K;
    } else {
        Arow = A + (size_t)(bm * 128 + lrow) * K;
    }
    const float* Brow = B + (size_t)(bn * 128 + lrow) * K;

    const int tx = tid & 15;              // N-direction
    const int ty = tid >> 4;              // M-direction

    float acc[8][8];
#pragma unroll
    for (int i = 0; i < 8; i++)
#pragma unroll
        for (int j = 0; j < 8; j++) acc[i][j] = 0.f;

    // prologue: load tile 0 into buffer 0
    {
        float4 a4 = *(const float4*)(Arow + lk);
        float4 b4 = *(const float4*)(Brow + lk);
        As[0][lk + 0][lrow] = a4.x; As[0][lk + 1][lrow] = a4.y;
        As[0][lk + 2][lrow] = a4.z; As[0][lk + 3][lrow] = a4.w;
        Bs[0][lk + 0][lrow] = b4.x; Bs[0][lk + 1][lrow] = b4.y;
        Bs[0][lk + 2][lrow] = b4.z; Bs[0][lk + 3][lrow] = b4.w;
    }
    __syncthreads();

    const int nt = K >> 3;
    for (int t = 0; t < nt; ++t) {
        const int cur = t & 1;
        float4 na, nb;
        if (t + 1 < nt) {
            na = *(const float4*)(Arow + (t + 1) * 8 + lk);
            nb = *(const float4*)(Brow + (t + 1) * 8 + lk);
        }
#pragma unroll
        for (int k = 0; k < 8; k++) {
            float af[8], bf[8];
            *(float4*)(af)     = *(const float4*)&As[cur][k][ty * 8];
            *(float4*)(af + 4) = *(const float4*)&As[cur][k][ty * 8 + 4];
            *(float4*)(bf)     = *(const float4*)&Bs[cur][k][tx * 8];
            *(float4*)(bf + 4) = *(const float4*)&Bs[cur][k][tx * 8 + 4];
#pragma unroll
            for (int i = 0; i < 8; i++)
#pragma unroll
                for (int j = 0; j < 8; j++)
                    acc[i][j] += af[i] * bf[j];
        }
        if (t + 1 < nt) {
            const int nxt = cur ^ 1;
            As[nxt][lk + 0][lrow] = na.x; As[nxt][lk + 1][lrow] = na.y;
            As[nxt][lk + 2][lrow] = na.z; As[nxt][lk + 3][lrow] = na.w;
            Bs[nxt][lk + 0][lrow] = nb.x; Bs[nxt][lk + 1][lrow] = nb.y;
            Bs[nxt][lk + 2][lrow] = nb.z; Bs[nxt][lk + 3][lrow] = nb.w;
            __syncthreads();
        }
    }

    // epilogue
    const int gm0 = bm * 128 + ty * 8;
    const int gn0 = bn * 128 + tx * 8;
    float bb[8];
    if (bias) {
        *(float4*)(bb)     = *(const float4*)(bias + gn0);
        *(float4*)(bb + 4) = *(const float4*)(bias + gn0 + 4);
    } else {
#pragma unroll
        for (int j = 0; j < 8; j++) bb[j] = 0.f;
    }
#pragma unroll
    for (int i = 0; i < 8; i++) {
        float4 v0, v1;
        v0.x = acc[i][0] + bb[0]; v0.y = acc[i][1] + bb[1];
        v0.z = acc[i][2] + bb[2]; v0.w = acc[i][3] + bb[3];
        v1.x = acc[i][4] + bb[4]; v1.y = acc[i][5] + bb[5];
        v1.z = acc[i][6] + bb[6]; v1.w = acc[i][7] + bb[7];
        float* crow = C + (size_t)(gm0 + i) * N + gn0;
        *(float4*)(crow)     = v0;
        *(float4*)(crow + 4) = v1;
    }
}

// ---------------------------------------------------------------------------
// tanh of x[0] -> th[0]
// ---------------------------------------------------------------------------
__global__ void tanh0_kernel()
{
    int i = blockIdx.x * blockDim.x + threadIdx.x;
    if (i < B_SZ * H_SZ) g_th[i] = tanhf(g_x[i]);
}

// ---------------------------------------------------------------------------
// One recurrence step:
//   th[s][b][n] = tanh( x[s][b][n] + sum_k th[s-1][b][k] * W_hh[n][k] )
// grid = 64 CTAs (16 output columns each), 256 threads = 16b x 16n, 1 out/thread.
// ---------------------------------------------------------------------------
__global__ void __launch_bounds__(256) step_kernel(const float* __restrict__ W_hh, int s)
{
    __shared__ float sA[16][68];   // th_prev tile [b][k], padded (68*4 bytes, 16B aligned rows)
    __shared__ float sW[16][68];   // W_hh tile [n_local][k]

    const float* th_prev = g_th + (size_t)(s - 1) * B_SZ * H_SZ;
    const float* x_s     = g_x  + (size_t)s * B_SZ * H_SZ;
    float*       th_out  = g_th + (size_t)s * B_SZ * H_SZ;

    const int tid = threadIdx.x;
    const int n0  = blockIdx.x * 16;

    const int lr = tid >> 4;          // 0..15 : row for cooperative loads
    const int lc = (tid & 15) << 2;   // 0..60 : float4 column

    const int n = tid & 15;           // output column (local)
    const int b = tid >> 4;           // output batch

    float acc = 0.f;

    for (int kt = 0; kt < H_SZ; kt += 64) {
        float4 a4 = *(const float4*)(th_prev + lr * H_SZ + kt + lc);
        float4 w4 = *(const float4*)(W_hh + (size_t)(n0 + lr) * H_SZ + kt + lc);
        __syncthreads();   // previous iteration's reads must finish
        *(float4*)&sA[lr][lc] = a4;
        *(float4*)&sW[lr][lc] = w4;
        __syncthreads();
#pragma unroll
        for (int k = 0; k < 64; k += 4) {
            float4 av = *(const float4*)&sA[b][k];
            float4 wv = *(const float4*)&sW[n][k];
            acc += av.x * wv.x;
            acc += av.y * wv.y;
            acc += av.z * wv.z;
            acc += av.w * wv.w;
        }
    }

    const int h = n0 + n;
    th_out[b * H_SZ + h] = tanhf(acc + x_s[b * H_SZ + h]);
}

// ---------------------------------------------------------------------------
// kernel_launch
// inputs order: inputs(int32 [S,B]), emb [V,E], W_in [H,E], W_hh [H,H],
//               W_out [V,H], b_out [V]; output: logits fp32 [S*B, V]
// ---------------------------------------------------------------------------
extern "C" void kernel_launch(void* const* d_in, const int* in_sizes, int n_in,
                              void* d_out, int out_size)
{
    (void)in_sizes; (void)n_in; (void)out_size;
    const int*   tokens = (const int*)  d_in[0];
    const float* emb    = (const float*)d_in[1];
    const float* W_in   = (const float*)d_in[2];
    const float* W_hh   = (const float*)d_in[3];
    const float* W_out  = (const float*)d_in[4];
    const float* b_out  = (const float*)d_in[5];
    float* out = (float*)d_out;

    float *gx = nullptr, *gth = nullptr;
    cudaGetSymbolAddress((void**)&gx,  g_x);
    cudaGetSymbolAddress((void**)&gth, g_th);

    // 1) x[s,b,h] = sum_e emb[tok[s,b], e] * W_in[h, e]
    //    M=4096, N=1024, K=512
    sgemm128_nt<true><<<dim3(H_SZ / 128, M_SZ / 128), 256>>>(
        emb, W_in, nullptr, tokens, gx, H_SZ, E_SZ);

    // 2) th[0] = tanh(x[0])
    tanh0_kernel<<<(B_SZ * H_SZ + 255) / 256, 256>>>();

    // 3) recurrence: s = 1..S-1
    for (int s = 1; s < S_LEN; ++s) {
        step_kernel<<<H_SZ / 16, 256>>>(W_hh, s);
    }

    // 4) logits[m, v] = sum_k th[m, k] * W_out[v, k] + b_out[v]
    //    M=4096, N=32000, K=1024
    sgemm128_nt<false><<<dim3(V_SZ / 128, M_SZ / 128), 256>>>(
        gth, W_out, b_out, nullptr, out, V_SZ, H_SZ);
}